// round 9
// baseline (speedup 1.0000x reference)
#include <cuda_runtime.h>
#include <cstdint>

// GumbelSinkhorn: B=128, N=512 rows (agents), M=512 cols (tasks), tau=1, 5 iters.
// Register-resident fused pairs, one row per warp. Sweeps use ex2 with log2e
// folded into precomputed reciprocal scales (g_ics). Column-sum inversion is
// fused into the producing kernel via a per-batch done-counter: the last CTA
// to finish a batch inverts its 512 csums (no extra launches, no consumer RCPs).

#define BB 128
#define NN 512
#define MM 512
#define LOG2E 1.4426950408889634f

__device__ float    g_E[(size_t)BB * NN * MM];  // exp-domain state
__device__ float    g_acc[5][BB * MM];          // raw colsum accumulators
__device__ float    g_ics[5][BB * MM];          // inverted scales (factor/csum)
__device__ unsigned g_done[5][BB];              // per-batch item counters
__device__ int      g_items[BB * 32];           // 16-row strips: (b<<5)|strip
__device__ int      g_cnt;

__device__ __forceinline__ float ex2f(float x) {
    float y;
    asm("ex2.approx.f32 %0, %1;" : "=f"(y) : "f"(x));
    return y;
}

__device__ __forceinline__ float warp_sum(float v) {
    v += __shfl_xor_sync(0xffffffffu, v, 16);
    v += __shfl_xor_sync(0xffffffffu, v, 8);
    v += __shfl_xor_sync(0xffffffffu, v, 4);
    v += __shfl_xor_sync(0xffffffffu, v, 2);
    v += __shfl_xor_sync(0xffffffffu, v, 1);
    return v;
}

// ---------------------------------------------------------------------------
// setup: zero accumulators + done counters; build active-strip list.
__global__ void setup_kernel(const int* __restrict__ fa,
                             const int* __restrict__ ta) {
    float4* p = (float4*)&g_acc[0][0];
    int total4 = 5 * BB * MM / 4;
    int gid = blockIdx.x * blockDim.x + threadIdx.x;
    for (int i = gid; i < total4; i += gridDim.x * blockDim.x)
        p[i] = make_float4(0.f, 0.f, 0.f, 0.f);
    if (gid < 5 * BB) (&g_done[0][0])[gid] = 0u;

    if (blockIdx.x == 0 && threadIdx.x < 32) {
        int lane = threadIdx.x;
        int carry = 0;
        for (int g = 0; g < 4; g++) {
            int b = g * 32 + lane;
            int na = fa[b], nt = ta[b];
            int c = (na > 0 && nt > 0) ? (na + 15) >> 4 : 0;   // 16-row strips
            int inc = c;
            #pragma unroll
            for (int d = 1; d < 32; d <<= 1) {
                int t = __shfl_up_sync(0xffffffffu, inc, d);
                if (lane >= d) inc += t;
            }
            int off = carry + inc - c;
            for (int s = 0; s < c; s++) g_items[off + s] = (b << 5) | s;
            carry += __shfl_sync(0xffffffffu, inc, 31);
        }
        if (lane == 0) g_cnt = carry;
    }
}

// ---------------------------------------------------------------------------
// Tail: column-partial reduce + atomic accumulate + (last finisher) inversion.
// sm[w][col] holds post-sweep2 values (zeros where inactive).
__device__ __forceinline__ void col_tail(float (*sm)[MM], int stage, float factor,
                                         int b, int na, int nt, int tid) {
    __syncthreads();
    float s = 0.f;
    #pragma unroll
    for (int ww = 0; ww < 16; ww++) s += sm[ww][tid];
    if (tid < nt) atomicAdd(&g_acc[stage][b * MM + tid], s);
    __threadfence();
    __shared__ bool last;
    if (tid == 0) {
        unsigned items = (unsigned)((na + 15) >> 4);
        unsigned v = atomicAdd(&g_done[stage][b], 1u);
        last = (v == items - 1u);
    }
    __syncthreads();
    if (last) {
        float ssum = g_acc[stage][b * MM + tid];
        g_ics[stage][b * MM + tid] = (ssum > 0.f) ? __fdividef(factor, ssum) : 0.f;
    }
    __syncthreads();
}

// ---------------------------------------------------------------------------
// I: E0=exp(logits); pass1 (axis2): E1=ex2(E0'*rinv); colsums -> acc[0]/ics[0].
__global__ void __launch_bounds__(512) init_pair_kernel(
        const float* __restrict__ logits,
        const int* __restrict__ fa,
        const int* __restrict__ ta) {
    __shared__ float sm[16][MM];
    int cnt = g_cnt;
    int tid = threadIdx.x, w = tid >> 5, lane = tid & 31;
    for (int it = blockIdx.x; it < cnt; it += gridDim.x) {
        int item = g_items[it];
        int b = item >> 5, r0 = (item & 31) << 4;
        int na = fa[b], nt = ta[b];
        float* Eb = g_E + (size_t)b * NN * MM;
        int gr = r0 + w;
        bool rowv = (gr < na);

        float4 v[4];
        float rowacc = 0.f;
        #pragma unroll
        for (int k = 0; k < 4; k++) {
            int cb = lane * 4 + k * 128;
            v[k] = make_float4(0.f, 0.f, 0.f, 0.f);
            if (rowv && cb < nt) {
                float4 e = *(const float4*)(logits + (size_t)b * NN * MM + gr * MM + cb);
                v[k].x = ex2f(e.x * LOG2E);
                v[k].y = (cb + 1 < nt) ? ex2f(e.y * LOG2E) : 0.f;
                v[k].z = (cb + 2 < nt) ? ex2f(e.z * LOG2E) : 0.f;
                v[k].w = (cb + 3 < nt) ? ex2f(e.w * LOG2E) : 0.f;
                rowacc += (v[k].x + v[k].y) + (v[k].z + v[k].w);
            }
        }
        float rinv = __fdividef(LOG2E, warp_sum(rowacc));
        #pragma unroll
        for (int k = 0; k < 4; k++) {
            int cb = lane * 4 + k * 128;
            float4 o = make_float4(0.f, 0.f, 0.f, 0.f);
            if (rowv && cb < nt) {
                o.x = ex2f(v[k].x * rinv);
                o.y = (cb + 1 < nt) ? ex2f(v[k].y * rinv) : 0.f;
                o.z = (cb + 2 < nt) ? ex2f(v[k].z * rinv) : 0.f;
                o.w = (cb + 3 < nt) ? ex2f(v[k].w * rinv) : 0.f;
                *(float4*)(Eb + gr * MM + cb) = o;
            }
            *(float4*)(&sm[w][cb]) = o;
        }
        col_tail(sm, 0, LOG2E, b, na, nt, tid);
    }
}

// ---------------------------------------------------------------------------
// P_p: sweep1 axis1 (v = ex2(E*ics[p])), sweep2 axis2; colsums -> acc/ics[p+1].
__global__ void __launch_bounds__(512) pair_kernel(
        int p,
        const int* __restrict__ fa,
        const int* __restrict__ ta) {
    __shared__ float sm[16][MM];
    const float* ICS = &g_ics[p][0];
    int stage = p + 1;
    float factor = (p == 3) ? 1.0f : LOG2E;
    int cnt = g_cnt;
    int tid = threadIdx.x, w = tid >> 5, lane = tid & 31;
    for (int it = blockIdx.x; it < cnt; it += gridDim.x) {
        int item = g_items[it];
        int b = item >> 5, r0 = (item & 31) << 4;
        int na = fa[b], nt = ta[b];
        const float* CS = ICS + b * MM;
        float*       Eb = g_E + (size_t)b * NN * MM;
        int gr = r0 + w;
        bool rowv = (gr < na);

        float4 v[4];
        float rowacc = 0.f;
        #pragma unroll
        for (int k = 0; k < 4; k++) {
            int cb = lane * 4 + k * 128;
            v[k] = make_float4(0.f, 0.f, 0.f, 0.f);
            if (rowv && cb < nt) {
                float4 s4 = *(const float4*)(CS + cb);
                float4 e  = *(const float4*)(Eb + gr * MM + cb);
                v[k].x = ex2f(e.x * s4.x);
                v[k].y = (cb + 1 < nt) ? ex2f(e.y * s4.y) : 0.f;
                v[k].z = (cb + 2 < nt) ? ex2f(e.z * s4.z) : 0.f;
                v[k].w = (cb + 3 < nt) ? ex2f(e.w * s4.w) : 0.f;
                rowacc += (v[k].x + v[k].y) + (v[k].z + v[k].w);
            }
        }
        float rinv = __fdividef(LOG2E, warp_sum(rowacc));
        #pragma unroll
        for (int k = 0; k < 4; k++) {
            int cb = lane * 4 + k * 128;
            float4 o = make_float4(0.f, 0.f, 0.f, 0.f);
            if (rowv && cb < nt) {
                o.x = ex2f(v[k].x * rinv);
                o.y = (cb + 1 < nt) ? ex2f(v[k].y * rinv) : 0.f;
                o.z = (cb + 2 < nt) ? ex2f(v[k].z * rinv) : 0.f;
                o.w = (cb + 3 < nt) ? ex2f(v[k].w * rinv) : 0.f;
                *(float4*)(Eb + gr * MM + cb) = o;
            }
            *(float4*)(&sm[w][cb]) = o;
        }
        col_tail(sm, stage, factor, b, na, nt, tid);
    }
}

// ---------------------------------------------------------------------------
// F: pass10 (axis1, no exp): out = E9 * ics[4] in mask, 0 outside. Full [N,M].
// E and ics are both 0 on inactive cells -> no per-element compares needed.
__global__ void __launch_bounds__(512) final_kernel(
        float* __restrict__ out,
        const int* __restrict__ fa,
        const int* __restrict__ ta) {
    int b = blockIdx.x >> 5, r0 = (blockIdx.x & 31) << 4;
    int na = fa[b], nt = ta[b];
    int tid = threadIdx.x, w = tid >> 5, lane = tid & 31;
    const float* Eb = g_E + (size_t)b * NN * MM;
    const float* CS = &g_ics[4][0] + b * MM;
    float*       Ob = out + (size_t)b * NN * MM;
    int gr = r0 + w;
    bool rowv = (gr < na);
    #pragma unroll
    for (int k = 0; k < 4; k++) {
        int cb = lane * 4 + k * 128;
        float4 o = make_float4(0.f, 0.f, 0.f, 0.f);
        if (rowv && cb < nt) {
            float4 s4 = *(const float4*)(CS + cb);
            float4 e  = *(const float4*)(Eb + gr * MM + cb);
            o.x = e.x * s4.x; o.y = e.y * s4.y;
            o.z = e.z * s4.z; o.w = e.w * s4.w;
        }
        *(float4*)(Ob + gr * MM + cb) = o;
    }
}

extern "C" void kernel_launch(void* const* d_in, const int* in_sizes, int n_in,
                              void* d_out, int out_size) {
    const float* logits = (const float*)d_in[0];
    const int*   fa     = (const int*)d_in[1];
    const int*   ta     = (const int*)d_in[2];
    float*       out    = (float*)d_out;

    setup_kernel<<<256, 256>>>(fa, ta);
    init_pair_kernel<<<2048, 512>>>(logits, fa, ta);
    for (int p = 0; p < 4; p++)
        pair_kernel<<<2048, 512>>>(p, fa, ta);
    final_kernel<<<4096, 512>>>(out, fa, ta);
}

// round 10
// speedup vs baseline: 1.1145x; 1.1145x over previous
#include <cuda_runtime.h>
#include <cstdint>

// GumbelSinkhorn: B=128, N=512 rows (agents), M=512 cols (tasks), tau=1, 5 iters.
// Register-resident fused pairs, one row per warp. Sweeps use ex2 with log2e
// folded into precomputed reciprocal column scales (g_ics). Column-sum
// inversion is fused into the producing kernel via a per-batch done-counter
// using scoped release/acquire atomics (NO gpu-scope fence -> no L1 flush).

#define BB 128
#define NN 512
#define MM 512
#define LOG2E 1.4426950408889634f

__device__ float    g_E[(size_t)BB * NN * MM];  // exp-domain state
__device__ float    g_acc[5][BB * MM];          // raw colsum accumulators
__device__ float    g_ics[5][BB * MM];          // inverted scales (factor/csum)
__device__ unsigned g_done[5][BB];              // per-batch item counters
__device__ int      g_items[BB * 32];           // 16-row strips: (b<<5)|strip
__device__ int      g_cnt;

__device__ __forceinline__ float ex2f(float x) {
    float y;
    asm("ex2.approx.f32 %0, %1;" : "=f"(y) : "f"(x));
    return y;
}
__device__ __forceinline__ unsigned atom_inc_acqrel(unsigned* p) {
    unsigned old;
    asm volatile("atom.add.acq_rel.gpu.global.u32 %0, [%1], 1;"
                 : "=r"(old) : "l"(p) : "memory");
    return old;
}
__device__ __forceinline__ float ld_cg(const float* p) {
    float v;
    asm volatile("ld.global.cg.f32 %0, [%1];" : "=f"(v) : "l"(p));
    return v;
}
__device__ __forceinline__ float warp_sum(float v) {
    v += __shfl_xor_sync(0xffffffffu, v, 16);
    v += __shfl_xor_sync(0xffffffffu, v, 8);
    v += __shfl_xor_sync(0xffffffffu, v, 4);
    v += __shfl_xor_sync(0xffffffffu, v, 2);
    v += __shfl_xor_sync(0xffffffffu, v, 1);
    return v;
}

// ---------------------------------------------------------------------------
// setup: zero accumulators + done counters; build active-strip list.
__global__ void setup_kernel(const int* __restrict__ fa,
                             const int* __restrict__ ta) {
    float4* p = (float4*)&g_acc[0][0];
    int total4 = 5 * BB * MM / 4;
    int gid = blockIdx.x * blockDim.x + threadIdx.x;
    for (int i = gid; i < total4; i += gridDim.x * blockDim.x)
        p[i] = make_float4(0.f, 0.f, 0.f, 0.f);
    if (gid < 5 * BB) (&g_done[0][0])[gid] = 0u;

    if (blockIdx.x == 0 && threadIdx.x < 32) {
        int lane = threadIdx.x;
        int carry = 0;
        for (int g = 0; g < 4; g++) {
            int b = g * 32 + lane;
            int na = fa[b], nt = ta[b];
            int c = (na > 0 && nt > 0) ? (na + 15) >> 4 : 0;   // 16-row strips
            int inc = c;
            #pragma unroll
            for (int d = 1; d < 32; d <<= 1) {
                int t = __shfl_up_sync(0xffffffffu, inc, d);
                if (lane >= d) inc += t;
            }
            int off = carry + inc - c;
            for (int s = 0; s < c; s++) g_items[off + s] = (b << 5) | s;
            carry += __shfl_sync(0xffffffffu, inc, 31);
        }
        if (lane == 0) g_cnt = carry;
    }
}

// ---------------------------------------------------------------------------
// Tail: column-partial reduce + relaxed atomic accumulate; the LAST finishing
// CTA for batch b (detected via acq_rel counter) inverts the 512 column sums.
__device__ __forceinline__ void col_tail(float (*sm)[MM], int stage, float factor,
                                         int b, int na, int nt, int tid) {
    __syncthreads();
    float s = 0.f;
    #pragma unroll
    for (int ww = 0; ww < 16; ww++) s += sm[ww][tid];
    if (tid < nt) atomicAdd(&g_acc[stage][b * MM + tid], s);
    __syncthreads();                       // all value atomics issued (CTA HB)
    __shared__ bool last;
    if (tid == 0) {
        unsigned items = (unsigned)((na + 15) >> 4);
        last = (atom_inc_acqrel(&g_done[stage][b]) == items - 1u);
    }
    __syncthreads();                       // broadcast `last`; protects sm reuse
    if (last) {
        float ssum = ld_cg(&g_acc[stage][b * MM + tid]);
        g_ics[stage][b * MM + tid] = (ssum > 0.f) ? __fdividef(factor, ssum) : 0.f;
    }
    __syncthreads();
}

// ---------------------------------------------------------------------------
// I: E0=exp(logits); pass1 (axis2): E1=ex2(E0*rinv); colsums -> acc[0]/ics[0].
__global__ void __launch_bounds__(512) init_pair_kernel(
        const float* __restrict__ logits,
        const int* __restrict__ fa,
        const int* __restrict__ ta) {
    __shared__ float sm[16][MM];
    int cnt = g_cnt;
    int tid = threadIdx.x, w = tid >> 5, lane = tid & 31;
    for (int it = blockIdx.x; it < cnt; it += gridDim.x) {
        int item = g_items[it];
        int b = item >> 5, r0 = (item & 31) << 4;
        int na = fa[b], nt = ta[b];
        float* Eb = g_E + (size_t)b * NN * MM;
        int gr = r0 + w;
        bool rowv = (gr < na);

        float4 v[4];
        float rowacc = 0.f;
        #pragma unroll
        for (int k = 0; k < 4; k++) {
            int cb = lane * 4 + k * 128;
            v[k] = make_float4(0.f, 0.f, 0.f, 0.f);
            if (rowv && cb < nt) {
                float4 e = *(const float4*)(logits + (size_t)b * NN * MM + gr * MM + cb);
                v[k].x = ex2f(e.x * LOG2E);
                v[k].y = (cb + 1 < nt) ? ex2f(e.y * LOG2E) : 0.f;
                v[k].z = (cb + 2 < nt) ? ex2f(e.z * LOG2E) : 0.f;
                v[k].w = (cb + 3 < nt) ? ex2f(e.w * LOG2E) : 0.f;
                rowacc += (v[k].x + v[k].y) + (v[k].z + v[k].w);
            }
        }
        float rinv = __fdividef(LOG2E, warp_sum(rowacc));
        #pragma unroll
        for (int k = 0; k < 4; k++) {
            int cb = lane * 4 + k * 128;
            float4 o = make_float4(0.f, 0.f, 0.f, 0.f);
            if (rowv && cb < nt) {
                o.x = ex2f(v[k].x * rinv);
                o.y = (cb + 1 < nt) ? ex2f(v[k].y * rinv) : 0.f;
                o.z = (cb + 2 < nt) ? ex2f(v[k].z * rinv) : 0.f;
                o.w = (cb + 3 < nt) ? ex2f(v[k].w * rinv) : 0.f;
                *(float4*)(Eb + gr * MM + cb) = o;
            }
            *(float4*)(&sm[w][cb]) = o;
        }
        col_tail(sm, 0, LOG2E, b, na, nt, tid);
    }
}

// ---------------------------------------------------------------------------
// P_p: sweep1 axis1 (v = ex2(E*ics[p])), sweep2 axis2; colsums -> acc/ics[p+1].
__global__ void __launch_bounds__(512) pair_kernel(
        int p,
        const int* __restrict__ fa,
        const int* __restrict__ ta) {
    __shared__ float sm[16][MM];
    const float* ICS = &g_ics[p][0];
    int stage = p + 1;
    float factor = (p == 3) ? 1.0f : LOG2E;
    int cnt = g_cnt;
    int tid = threadIdx.x, w = tid >> 5, lane = tid & 31;
    for (int it = blockIdx.x; it < cnt; it += gridDim.x) {
        int item = g_items[it];
        int b = item >> 5, r0 = (item & 31) << 4;
        int na = fa[b], nt = ta[b];
        const float* CS = ICS + b * MM;
        float*       Eb = g_E + (size_t)b * NN * MM;
        int gr = r0 + w;
        bool rowv = (gr < na);

        float4 v[4];
        float rowacc = 0.f;
        #pragma unroll
        for (int k = 0; k < 4; k++) {
            int cb = lane * 4 + k * 128;
            v[k] = make_float4(0.f, 0.f, 0.f, 0.f);
            if (rowv && cb < nt) {
                float4 s4 = *(const float4*)(CS + cb);
                float4 e  = *(const float4*)(Eb + gr * MM + cb);
                v[k].x = ex2f(e.x * s4.x);
                v[k].y = (cb + 1 < nt) ? ex2f(e.y * s4.y) : 0.f;
                v[k].z = (cb + 2 < nt) ? ex2f(e.z * s4.z) : 0.f;
                v[k].w = (cb + 3 < nt) ? ex2f(e.w * s4.w) : 0.f;
                rowacc += (v[k].x + v[k].y) + (v[k].z + v[k].w);
            }
        }
        float rinv = __fdividef(LOG2E, warp_sum(rowacc));
        #pragma unroll
        for (int k = 0; k < 4; k++) {
            int cb = lane * 4 + k * 128;
            float4 o = make_float4(0.f, 0.f, 0.f, 0.f);
            if (rowv && cb < nt) {
                o.x = ex2f(v[k].x * rinv);
                o.y = (cb + 1 < nt) ? ex2f(v[k].y * rinv) : 0.f;
                o.z = (cb + 2 < nt) ? ex2f(v[k].z * rinv) : 0.f;
                o.w = (cb + 3 < nt) ? ex2f(v[k].w * rinv) : 0.f;
                *(float4*)(Eb + gr * MM + cb) = o;
            }
            *(float4*)(&sm[w][cb]) = o;
        }
        col_tail(sm, stage, factor, b, na, nt, tid);
    }
}

// ---------------------------------------------------------------------------
// F: pass10 (axis1, no exp): out = E9 * ics[4] in mask, 0 outside. Full [N,M].
__global__ void __launch_bounds__(512) final_kernel(
        float* __restrict__ out,
        const int* __restrict__ fa,
        const int* __restrict__ ta) {
    int b = blockIdx.x >> 5, r0 = (blockIdx.x & 31) << 4;
    int na = fa[b], nt = ta[b];
    int tid = threadIdx.x, w = tid >> 5, lane = tid & 31;
    const float* Eb = g_E + (size_t)b * NN * MM;
    const float* CS = &g_ics[4][0] + b * MM;
    float*       Ob = out + (size_t)b * NN * MM;
    int gr = r0 + w;
    bool rowv = (gr < na);
    #pragma unroll
    for (int k = 0; k < 4; k++) {
        int cb = lane * 4 + k * 128;
        float4 o = make_float4(0.f, 0.f, 0.f, 0.f);
        if (rowv && cb < nt) {
            float4 s4 = *(const float4*)(CS + cb);
            float4 e  = *(const float4*)(Eb + gr * MM + cb);
            o.x = e.x * s4.x; o.y = e.y * s4.y;
            o.z = e.z * s4.z; o.w = e.w * s4.w;
        }
        *(float4*)(Ob + gr * MM + cb) = o;
    }
}

extern "C" void kernel_launch(void* const* d_in, const int* in_sizes, int n_in,
                              void* d_out, int out_size) {
    const float* logits = (const float*)d_in[0];
    const int*   fa     = (const int*)d_in[1];
    const int*   ta     = (const int*)d_in[2];
    float*       out    = (float*)d_out;

    setup_kernel<<<256, 256>>>(fa, ta);
    init_pair_kernel<<<2048, 512>>>(logits, fa, ta);
    for (int p = 0; p < 4; p++)
        pair_kernel<<<2048, 512>>>(p, fa, ta);
    final_kernel<<<4096, 512>>>(out, fa, ta);
}